// round 5
// baseline (speedup 1.0000x reference)
#include <cuda_runtime.h>
#include <math.h>
#include <stdint.h>

// Problem constants
constexpr int Bn = 8, Sn = 1024, Dn = 512, Hn = 8, HD = 64, Fn = 2048;
constexpr int Mtok = Bn * Sn; // 8192
constexpr int D3 = 3 * Dn;    // 1536

// Scratch (static device globals; no runtime allocation)
__device__ float gQKV [(size_t)Mtok * D3];          // packed Q|K|V rows
__device__ float gWcat[Dn * D3];
__device__ float gBcat[D3];
__device__ float gCtx[Mtok * Dn];
__device__ float gY  [Mtok * Dn];
__device__ float gX1 [Mtok * Dn];
__device__ float gH1 [(size_t)Mtok * Fn];
__device__ float gY2 [Mtok * Dn];

enum { EPI_NONE = 0, EPI_BIAS = 1, EPI_MISH = 2 };

__device__ __forceinline__ float mish_f(float v) {
    float sp = (v > 20.f) ? v : log1pf(expf(v));
    return v * tanhf(sp);
}

__device__ __forceinline__ float to_tf32(float x) {
    float r;
    asm("cvt.rna.tf32.f32 %0, %1;" : "=f"(r) : "f"(x));
    return r;
}

__device__ __forceinline__ void cpa16(float* smem_dst, const float* gsrc) {
    uint32_t a = (uint32_t)__cvta_generic_to_shared(smem_dst);
    asm volatile("cp.async.cg.shared.global [%0], [%1], 16;" :: "r"(a), "l"(gsrc));
}
__device__ __forceinline__ void cp_commit() {
    asm volatile("cp.async.commit_group;");
}
template <int NN>
__device__ __forceinline__ void cp_wait() {
    asm volatile("cp.async.wait_group %0;" :: "n"(NN));
}

__device__ __forceinline__ void mma_tf32(float* acc, const uint32_t* a, const uint32_t* b) {
    asm volatile(
        "mma.sync.aligned.m16n8k8.row.col.f32.tf32.tf32.f32 "
        "{%0,%1,%2,%3}, {%4,%5,%6,%7}, {%8,%9}, {%0,%1,%2,%3};"
        : "+f"(acc[0]), "+f"(acc[1]), "+f"(acc[2]), "+f"(acc[3])
        : "r"(a[0]), "r"(a[1]), "r"(a[2]), "r"(a[3]), "r"(b[0]), "r"(b[1]));
}

// Host/device-consistent smem sizing (3-stage pipeline) for tgemm
constexpr int ASTRc = 20;
constexpr size_t tg_smem_bytes(int BM, int BN, bool BT) {
    int bs = BT ? BN * ASTRc : 16 * (BN + 8);
    return (size_t)(BM * ASTRc + bs) * 3 * sizeof(float);
}

// ---------------------------------------------------------------------------
// tf32 tensor-core GEMM, 3-stage cp.async pipeline: C = A @ B (+bias)(+mish).
// ---------------------------------------------------------------------------
template <int BM, int BN, int WM, int WN, int EPI, bool BTRANS>
__global__ __launch_bounds__(256, 2)
void tgemm(const float* __restrict__ Ag, const float* __restrict__ Bg,
           const float* __restrict__ bias, float* __restrict__ Cg,
           int M, int N, int K, int lda, int ldb, int ldc)
{
    constexpr int BK = 16;
    constexpr int WARPS_N = BN / WN;
    constexpr int MI = WM / 16;
    constexpr int NI = WN / 8;
    constexpr int ASTR = ASTRc;              // 20
    constexpr int BNP  = BN + 8;
    constexpr int BS_ELEMS = BTRANS ? BN * ASTR : BK * BNP;

    extern __shared__ __align__(16) float dsm[];
    float* AsBase = dsm;
    float* BsBase = dsm + 3 * BM * ASTR;

    const float* A = Ag;
    const float* B = Bg;
    float*       C = Cg;

    const int tid  = threadIdx.x;
    const int lane = tid & 31;
    const int w    = tid >> 5;
    const int gid  = lane >> 2;
    const int tig  = lane & 3;
    const int wm0  = (w / WARPS_N) * WM;
    const int wn0  = (w % WARPS_N) * WN;
    const int m0   = blockIdx.y * BM;
    const int n0   = blockIdx.x * BN;

    float acc[MI][NI][4];
#pragma unroll
    for (int i = 0; i < MI; i++)
#pragma unroll
        for (int j = 0; j < NI; j++)
#pragma unroll
            for (int c = 0; c < 4; c++) acc[i][j][c] = 0.f;

    const int nTiles = K / BK;

    auto load_tile = [&](int kt, int buf) {
        float* As = AsBase + buf * (BM * ASTR);
        float* Bs = BsBase + buf * BS_ELEMS;
#pragma unroll
        for (int i = tid; i < BM * 4; i += 256) {
            int m = i >> 2, kc = (i & 3) * 4;
            cpa16(&As[m * ASTR + kc], A + (size_t)(m0 + m) * lda + kt * BK + kc);
        }
        if (BTRANS) {
#pragma unroll
            for (int i = tid; i < BN * 4; i += 256) {
                int n = i >> 2, kc = (i & 3) * 4;
                cpa16(&Bs[n * ASTR + kc], B + (size_t)(n0 + n) * ldb + kt * BK + kc);
            }
        } else {
#pragma unroll
            for (int i = tid; i < BK * BN / 4; i += 256) {
                int kr = i / (BN / 4), nq = (i % (BN / 4)) * 4;
                cpa16(&Bs[kr * BNP + nq], B + (size_t)(kt * BK + kr) * ldb + n0 + nq);
            }
        }
        cp_commit();
    };

    load_tile(0, 0);
    load_tile(1, 1);

    for (int kt = 0; kt < nTiles; kt++) {
        if (kt + 1 >= nTiles) cp_wait<0>(); else cp_wait<1>();
        __syncthreads();
        if (kt + 2 < nTiles) load_tile(kt + 2, (kt + 2) % 3);

        int buf = kt % 3;
        const float* As = AsBase + buf * (BM * ASTR);
        const float* Bs = BsBase + buf * BS_ELEMS;

#pragma unroll
        for (int ks = 0; ks < BK; ks += 8) {
            uint32_t af[MI][4], bf[NI][2];
#pragma unroll
            for (int mi = 0; mi < MI; mi++) {
                const float* ap = As + (wm0 + mi * 16 + gid) * ASTR + ks + tig;
                af[mi][0] = __float_as_uint(to_tf32(ap[0]));
                af[mi][1] = __float_as_uint(to_tf32(ap[8 * ASTR]));
                af[mi][2] = __float_as_uint(to_tf32(ap[4]));
                af[mi][3] = __float_as_uint(to_tf32(ap[8 * ASTR + 4]));
            }
#pragma unroll
            for (int ni = 0; ni < NI; ni++) {
                if (BTRANS) {
                    const float* bp = Bs + (wn0 + ni * 8 + gid) * ASTR + ks + tig;
                    bf[ni][0] = __float_as_uint(to_tf32(bp[0]));
                    bf[ni][1] = __float_as_uint(to_tf32(bp[4]));
                } else {
                    const float* bp = Bs + (ks + tig) * BNP + wn0 + ni * 8 + gid;
                    bf[ni][0] = __float_as_uint(to_tf32(bp[0]));
                    bf[ni][1] = __float_as_uint(to_tf32(bp[4 * BNP]));
                }
            }
#pragma unroll
            for (int mi = 0; mi < MI; mi++)
#pragma unroll
                for (int ni = 0; ni < NI; ni++)
                    mma_tf32(acc[mi][ni], af[mi], bf[ni]);
        }
    }

#pragma unroll
    for (int mi = 0; mi < MI; mi++) {
#pragma unroll
        for (int ni = 0; ni < NI; ni++) {
            int row = m0 + wm0 + mi * 16 + gid;
            int col = n0 + wn0 + ni * 8 + tig * 2;
            float b0 = 0.f, b1 = 0.f;
            if (EPI >= 1) { b0 = bias[col]; b1 = bias[col + 1]; }
            float v0 = acc[mi][ni][0] + b0, v1 = acc[mi][ni][1] + b1;
            float v2 = acc[mi][ni][2] + b0, v3 = acc[mi][ni][3] + b1;
            if (EPI == 2) { v0 = mish_f(v0); v1 = mish_f(v1); v2 = mish_f(v2); v3 = mish_f(v3); }
            *(float2*)(C + (size_t)row * ldc + col)       = make_float2(v0, v1);
            *(float2*)(C + (size_t)(row + 8) * ldc + col) = make_float2(v2, v3);
        }
    }
}

// ---------------------------------------------------------------------------
// Fused attention: per CTA = one (b,h) and 32 query rows.
// Phase 1: S = Q@K^T into smem (raw scores, fp32).
// Phase 2: entmax-1.5 tau per row (warp/row), p=(z-tau)+^2 written in place.
// Phase 3: ctx = P@V.
// Scores never touch HBM; K/V stream from L2.
// ---------------------------------------------------------------------------
constexpr int QT = 32;          // query rows per CTA
constexpr int SSTR = 1032;      // S smem row stride (floats)
constexpr int KSTR = 68;        // Q/K tile row stride
constexpr int VSTR = 72;        // V tile row stride (64 + 8)
constexpr int KCH = 128;        // key rows per phase-1 chunk
constexpr size_t FA_SMEM =
    (size_t)(QT * SSTR + QT * KSTR + 2 * KCH * KSTR) * sizeof(float);

__global__ __launch_bounds__(256, 1)
void fused_attn(const float* __restrict__ qkv, float* __restrict__ ctx)
{
    extern __shared__ __align__(16) float sm[];
    float* Ssm = sm;                       // QT * SSTR
    float* Qsm = Ssm + QT * SSTR;          // QT * KSTR
    float* Kt  = Qsm + QT * KSTR;          // 2 * KCH * KSTR (reused as V staging)

    const int tid  = threadIdx.x;
    const int lane = tid & 31;
    const int w    = tid >> 5;
    const int gid  = lane >> 2;
    const int tig  = lane & 3;
    const int bh = blockIdx.y, bb = bh >> 3, hh = bh & 7;
    const int q0 = blockIdx.x * QT;

    const float* Qg = qkv + (size_t)(bb * Sn + q0) * D3 + hh * HD;
    const float* Kg = qkv + (size_t)bb * Sn * D3 + Dn + hh * HD;
    const float* Vg = qkv + (size_t)bb * Sn * D3 + 2 * Dn + hh * HD;

    auto loadK = [&](int ch, int buf) {
        float* dst = Kt + buf * (KCH * KSTR);
        const float* src = Kg + (size_t)(ch * KCH) * D3;
#pragma unroll
        for (int i = tid; i < KCH * 16; i += 256) {
            int r = i >> 4, c = (i & 15) * 4;
            cpa16(&dst[r * KSTR + c], src + (size_t)r * D3 + c);
        }
        cp_commit();
    };

    // Q tile + K chunk 0 (one async group)
#pragma unroll
    for (int i = tid; i < QT * 16; i += 256) {
        int r = i >> 4, c = (i & 15) * 4;
        cpa16(&Qsm[r * KSTR + c], Qg + (size_t)r * D3 + c);
    }
    loadK(0, 0);

    // ---- Phase 1: scores (M=32, N=1024 in 8 chunks of 128, K=64) ----
    {
        const int wm = (w & 1) * 16, wn = (w >> 1) * 32;   // 2x4 warps, NI=4
        for (int ch = 0; ch < 8; ch++) {
            if (ch + 1 < 8) { loadK(ch + 1, (ch + 1) & 1); cp_wait<1>(); }
            else cp_wait<0>();
            __syncthreads();
            const float* Kb = Kt + (ch & 1) * (KCH * KSTR);

            float acc[4][4];
#pragma unroll
            for (int ni = 0; ni < 4; ni++)
#pragma unroll
                for (int c = 0; c < 4; c++) acc[ni][c] = 0.f;

#pragma unroll
            for (int ks = 0; ks < 64; ks += 8) {
                uint32_t af[4], bf[4][2];
                const float* ap = Qsm + (wm + gid) * KSTR + ks + tig;
                af[0] = __float_as_uint(to_tf32(ap[0]));
                af[1] = __float_as_uint(to_tf32(ap[8 * KSTR]));
                af[2] = __float_as_uint(to_tf32(ap[4]));
                af[3] = __float_as_uint(to_tf32(ap[8 * KSTR + 4]));
#pragma unroll
                for (int ni = 0; ni < 4; ni++) {
                    const float* bp = Kb + (wn + ni * 8 + gid) * KSTR + ks + tig;
                    bf[ni][0] = __float_as_uint(to_tf32(bp[0]));
                    bf[ni][1] = __float_as_uint(to_tf32(bp[4]));
                }
#pragma unroll
                for (int ni = 0; ni < 4; ni++) mma_tf32(acc[ni], af, bf[ni]);
            }
#pragma unroll
            for (int ni = 0; ni < 4; ni++) {
                int r = wm + gid, col = ch * 128 + wn + ni * 8 + tig * 2;
                *(float2*)&Ssm[r * SSTR + col]       = make_float2(acc[ni][0], acc[ni][1]);
                *(float2*)&Ssm[(r + 8) * SSTR + col] = make_float2(acc[ni][2], acc[ni][3]);
            }
            __syncthreads();
        }
    }

    // prefetch V chunk 0 (overlaps tau solve); reuses Kt region
    float* Vs = Kt;
    auto loadV = [&](int kt, int buf) {
        float* dst = Vs + buf * (32 * VSTR);
        const float* src = Vg + (size_t)(kt * 32) * D3;
#pragma unroll
        for (int i = tid; i < 32 * 16; i += 256) {
            int r = i >> 4, c = (i & 15) * 4;
            cpa16(&dst[r * VSTR + c], src + (size_t)r * D3 + c);
        }
        cp_commit();
    };
    loadV(0, 0);

    // ---- Phase 2: entmax tau per row; warp w owns rows 4w..4w+3 ----
    for (int i = 0; i < 4; i++) {
        int r = w * 4 + i;
        float z[32];
#pragma unroll
        for (int j = 0; j < 32; j++) z[j] = Ssm[r * SSTR + lane + 32 * j] * 0.0625f;

        float m = z[0];
#pragma unroll
        for (int j = 1; j < 32; j++) m = fmaxf(m, z[j]);
#pragma unroll
        for (int o = 16; o > 0; o >>= 1) m = fmaxf(m, __shfl_xor_sync(0xffffffffu, m, o));
#pragma unroll
        for (int j = 0; j < 32; j++) z[j] -= m;

        float lo = -1.f, hi = 0.f;
#pragma unroll
        for (int it = 0; it < 5; it++) {
            float mid = 0.5f * (lo + hi);
            float s = 0.f;
#pragma unroll
            for (int j = 0; j < 32; j++) {
                float d = fmaxf(z[j] - mid, 0.f);
                s = fmaf(d, d, s);
            }
#pragma unroll
            for (int o = 16; o > 0; o >>= 1) s += __shfl_xor_sync(0xffffffffu, s, o);
            if (s > 1.f) lo = mid; else hi = mid;
        }

        float t = lo;
#pragma unroll
        for (int it = 0; it < 4; it++) {
            float s1 = 0.f, s2 = 0.f;
#pragma unroll
            for (int j = 0; j < 32; j++) {
                float d = fmaxf(z[j] - t, 0.f);
                s1 += d;
                s2 = fmaf(d, d, s2);
            }
#pragma unroll
            for (int o = 16; o > 0; o >>= 1) {
                s1 += __shfl_xor_sync(0xffffffffu, s1, o);
                s2 += __shfl_xor_sync(0xffffffffu, s2, o);
            }
            t += (s2 - 1.f) / (2.f * s1);
        }

        float c = 0.f, s1 = 0.f, s2 = 0.f;
#pragma unroll
        for (int j = 0; j < 32; j++) {
            if (z[j] > t) { c += 1.f; s1 += z[j]; s2 = fmaf(z[j], z[j], s2); }
        }
#pragma unroll
        for (int o = 16; o > 0; o >>= 1) {
            c  += __shfl_xor_sync(0xffffffffu, c,  o);
            s1 += __shfl_xor_sync(0xffffffffu, s1, o);
            s2 += __shfl_xor_sync(0xffffffffu, s2, o);
        }
        float disc = fmaxf(s1 * s1 - c * (s2 - 1.f), 0.f);
        float tau  = (s1 - sqrtf(disc)) / c;

#pragma unroll
        for (int j = 0; j < 32; j++) {
            float d = fmaxf(z[j] - tau, 0.f);
            Ssm[r * SSTR + lane + 32 * j] = d * d;
        }
    }

    // ---- Phase 3: ctx = P @ V (M=32, N=64, K=1024 in 32-row chunks) ----
    {
        const int wm = (w & 1) * 16, wn = (w >> 1) * 16;   // 2x4 warps, NI=2
        float acc[2][4];
#pragma unroll
        for (int ni = 0; ni < 2; ni++)
#pragma unroll
            for (int c = 0; c < 4; c++) acc[ni][c] = 0.f;

        for (int kt = 0; kt < 32; kt++) {
            if (kt + 1 < 32) { loadV(kt + 1, (kt + 1) & 1); cp_wait<1>(); }
            else cp_wait<0>();
            __syncthreads();
            const float* Vb = Vs + (kt & 1) * (32 * VSTR);

#pragma unroll
            for (int ks = 0; ks < 32; ks += 8) {
                uint32_t af[4], bf[2][2];
                const float* ap = Ssm + (wm + gid) * SSTR + kt * 32 + ks + tig;
                af[0] = __float_as_uint(to_tf32(ap[0]));
                af[1] = __float_as_uint(to_tf32(ap[8 * SSTR]));
                af[2] = __float_as_uint(to_tf32(ap[4]));
                af[3] = __float_as_uint(to_tf32(ap[8 * SSTR + 4]));
#pragma unroll
                for (int ni = 0; ni < 2; ni++) {
                    const float* bp = Vb + (ks + tig) * VSTR + wn + ni * 8 + gid;
                    bf[ni][0] = __float_as_uint(to_tf32(bp[0]));
                    bf[ni][1] = __float_as_uint(to_tf32(bp[4 * VSTR]));
                }
#pragma unroll
                for (int ni = 0; ni < 2; ni++) mma_tf32(acc[ni], af, bf[ni]);
            }
            __syncthreads();
        }

#pragma unroll
        for (int ni = 0; ni < 2; ni++) {
            int r = wm + gid;
            int col = hh * HD + wn + ni * 8 + tig * 2;
            float* cp0 = ctx + (size_t)(bb * Sn + q0 + r) * Dn + col;
            *(float2*)cp0              = make_float2(acc[ni][0], acc[ni][1]);
            *(float2*)(cp0 + 8 * Dn)   = make_float2(acc[ni][2], acc[ni][3]);
        }
    }
}

// ---------------------------------------------------------------------------
// Pack Wq|Wk|Wv -> gWcat [512][1536], biases -> gBcat [1536]
// ---------------------------------------------------------------------------
__global__ __launch_bounds__(256)
void concat_qkv(const float* __restrict__ Wq, const float* __restrict__ Wk,
                const float* __restrict__ Wv,
                const float* __restrict__ bq, const float* __restrict__ bk,
                const float* __restrict__ bv,
                float* __restrict__ Wcat, float* __restrict__ bcat)
{
    int i = blockIdx.x * 256 + threadIdx.x;
    if (i < Dn * Dn) {
        int k = i >> 9, n = i & 511;
        Wcat[k * D3 + n]          = Wq[i];
        Wcat[k * D3 + Dn + n]     = Wk[i];
        Wcat[k * D3 + 2 * Dn + n] = Wv[i];
    }
    if (i < Dn) {
        bcat[i]          = bq[i];
        bcat[Dn + i]     = bk[i];
        bcat[2 * Dn + i] = bv[i];
    }
}

// ---------------------------------------------------------------------------
__device__ __forceinline__ float blkRedSum(float v, float* sm) {
#pragma unroll
    for (int o = 16; o > 0; o >>= 1) v += __shfl_xor_sync(0xffffffffu, v, o);
    int nw = blockDim.x >> 5;
    if ((threadIdx.x & 31) == 0) sm[threadIdx.x >> 5] = v;
    __syncthreads();
    if (threadIdx.x == 0) {
        float s = sm[0];
        for (int i = 1; i < nw; i++) s += sm[i];
        sm[0] = s;
    }
    __syncthreads();
    float r = sm[0];
    __syncthreads();
    return r;
}

// out = residual + LayerNorm(y) * g + b   (rows of 512, eps=1e-5, biased var)
__global__ __launch_bounds__(128)
void add_ln_kernel(const float* __restrict__ Y, const float* __restrict__ R,
                   const float* __restrict__ g, const float* __restrict__ b,
                   float* __restrict__ O)
{
    __shared__ float sm[4];
    size_t row = blockIdx.x;
    const float* y = Y + row * 512;
    int tid = threadIdx.x;

    float v[4];
#pragma unroll
    for (int j = 0; j < 4; j++) v[j] = y[tid + j * 128];
    float s = 0.f, ss = 0.f;
#pragma unroll
    for (int j = 0; j < 4; j++) { s += v[j]; ss = fmaf(v[j], v[j], ss); }
    s  = blkRedSum(s,  sm);
    ss = blkRedSum(ss, sm);
    float mean = s * (1.f / 512.f);
    float var  = ss * (1.f / 512.f) - mean * mean;
    float rstd = rsqrtf(var + 1e-5f);
#pragma unroll
    for (int j = 0; j < 4; j++) {
        int c = tid + j * 128;
        O[row * 512 + c] = R[row * 512 + c] + (v[j] - mean) * rstd * g[c] + b[c];
    }
}

// ---------------------------------------------------------------------------
extern "C" void kernel_launch(void* const* d_in, const int* in_sizes, int n_in,
                              void* d_out, int out_size)
{
    const float* x   = (const float*)d_in[0];
    const float* Wq  = (const float*)d_in[1];  const float* bq  = (const float*)d_in[2];
    const float* Wk  = (const float*)d_in[3];  const float* bk  = (const float*)d_in[4];
    const float* Wv  = (const float*)d_in[5];  const float* bv  = (const float*)d_in[6];
    const float* Wo  = (const float*)d_in[7];  const float* bo  = (const float*)d_in[8];
    const float* g1  = (const float*)d_in[9];  const float* be1 = (const float*)d_in[10];
    const float* W1  = (const float*)d_in[11]; const float* b1  = (const float*)d_in[12];
    const float* W2  = (const float*)d_in[13]; const float* b2  = (const float*)d_in[14];
    const float* g2  = (const float*)d_in[15]; const float* be2 = (const float*)d_in[16];
    float* out = (float*)d_out;

    float *qkv, *wcat, *bcat, *ctx, *y, *x1, *h1, *y2;
    cudaGetSymbolAddress((void**)&qkv,  gQKV);
    cudaGetSymbolAddress((void**)&wcat, gWcat);
    cudaGetSymbolAddress((void**)&bcat, gBcat);
    cudaGetSymbolAddress((void**)&ctx,  gCtx);
    cudaGetSymbolAddress((void**)&y,    gY);
    cudaGetSymbolAddress((void**)&x1,   gX1);
    cudaGetSymbolAddress((void**)&h1,   gH1);
    cudaGetSymbolAddress((void**)&y2,   gY2);

    // Opt in to >48KB dynamic smem
    constexpr size_t SM_BIG = tg_smem_bytes(128, 128, false);
    cudaFuncSetAttribute((const void*)tgemm<128,128,64,32,EPI_BIAS,false>,
                         cudaFuncAttributeMaxDynamicSharedMemorySize, (int)SM_BIG);
    cudaFuncSetAttribute((const void*)tgemm<128,128,64,32,EPI_MISH,false>,
                         cudaFuncAttributeMaxDynamicSharedMemorySize, (int)SM_BIG);
    cudaFuncSetAttribute((const void*)fused_attn,
                         cudaFuncAttributeMaxDynamicSharedMemorySize, (int)FA_SMEM);

    // 0) pack QKV weights/biases
    concat_qkv<<<(Dn * Dn + 255) / 256, 256>>>(Wq, Wk, Wv, bq, bk, bv, wcat, bcat);

    // 1) QKV in one GEMM: [8192,512] @ [512,1536] + bias -> gQKV
    tgemm<128,128,64,32,EPI_BIAS,false>
        <<<dim3(D3 / 128, Mtok / 128, 1), 256, SM_BIG>>>(
        x, wcat, bcat, qkv, Mtok, D3, Dn, Dn, D3, D3);

    // 2-4) fused attention: scores + entmax + P@V, no HBM score tensor
    fused_attn<<<dim3(Sn / QT, Bn * Hn), 256, FA_SMEM>>>(qkv, ctx);

    // 5) y = ctx @ Wo + bo
    tgemm<128,128,64,32,EPI_BIAS,false>
        <<<dim3(Dn / 128, Mtok / 128, 1), 256, SM_BIG>>>(
        ctx, Wo, bo, y, Mtok, Dn, Dn, Dn, Dn, Dn);

    // 6) x1 = x + LN(y)
    add_ln_kernel<<<Mtok, 128>>>(y, x, g1, be1, x1);

    // 7) h1 = mish(x1 @ W1 + b1)  [8192,2048]
    tgemm<128,128,64,32,EPI_MISH,false>
        <<<dim3(Fn / 128, Mtok / 128, 1), 256, SM_BIG>>>(
        x1, W1, b1, h1, Mtok, Fn, Dn, Dn, Fn, Fn);

    // 8) y2 = h1 @ W2 + b2  [8192,512]
    tgemm<128,128,64,32,EPI_BIAS,false>
        <<<dim3(Dn / 128, Mtok / 128, 1), 256, SM_BIG>>>(
        h1, W2, b2, y2, Mtok, Dn, Fn, Fn, Dn, Dn);

    // 9) out = x1 + LN(y2)
    add_ln_kernel<<<Mtok, 128>>>(y2, x1, g2, be2, out);
}

// round 6
// speedup vs baseline: 1.0955x; 1.0955x over previous
#include <cuda_runtime.h>
#include <math.h>
#include <stdint.h>

// Problem constants
constexpr int Bn = 8, Sn = 1024, Dn = 512, Hn = 8, HD = 64, Fn = 2048;
constexpr int Mtok = Bn * Sn; // 8192
constexpr int D3 = 3 * Dn;    // 1536

// Scratch (static device globals; no runtime allocation)
__device__ float gQKV [(size_t)Mtok * D3];          // packed Q|K|V rows
__device__ float gWcat[Dn * D3];
__device__ float gBcat[D3];
__device__ float gS  [(size_t)Bn * Hn * Sn * Sn];   // 256 MB raw scores
__device__ float gTau[Bn * Hn * Sn];                // per-row threshold (m + tau*)
__device__ float gCtx[Mtok * Dn];
__device__ float gY  [Mtok * Dn];
__device__ float gX1 [Mtok * Dn];
__device__ float gH1 [(size_t)Mtok * Fn];
__device__ float gY2 [Mtok * Dn];

enum { EPI_NONE = 0, EPI_BIAS = 1, EPI_MISH = 2 };

__device__ __forceinline__ float mish_f(float v) {
    float sp = (v > 20.f) ? v : log1pf(expf(v));
    return v * tanhf(sp);
}

__device__ __forceinline__ float to_tf32(float x) {
    float r;
    asm("cvt.rna.tf32.f32 %0, %1;" : "=f"(r) : "f"(x));
    return r;
}

__device__ __forceinline__ void cpa16(float* smem_dst, const float* gsrc) {
    uint32_t a = (uint32_t)__cvta_generic_to_shared(smem_dst);
    asm volatile("cp.async.cg.shared.global [%0], [%1], 16;" :: "r"(a), "l"(gsrc));
}
__device__ __forceinline__ void cp_commit() {
    asm volatile("cp.async.commit_group;");
}
template <int NN>
__device__ __forceinline__ void cp_wait() {
    asm volatile("cp.async.wait_group %0;" :: "n"(NN));
}

// Host/device-consistent smem sizing (4-stage pipeline)
constexpr int ASTRc = 20;
constexpr int STAGES = 4;
constexpr size_t tg_smem_bytes(int BM, int BN, bool BT) {
    int bs = BT ? BN * ASTRc : 16 * (BN + 8);
    return (size_t)(BM * ASTRc + bs) * STAGES * sizeof(float);
}

// ---------------------------------------------------------------------------
// tf32 tensor-core GEMM, 4-stage cp.async pipeline: C = A @ B (+bias)(+mish).
// BTRANS: B stored [N,K] (K contiguous) -> C = A @ B^T.
// ENTA:   A element transform p = (max(a*0.0625 - T[row], 0))^2 at fragment
//         load (entmax apply fused into attn@V).
// Block BM x BN, BK=16, 256 threads (8 warps), warp tile WM x WN,
// mma.sync.m16n8k8 tf32. Requires M%BM==0, N%BN==0, K%16==0, nTiles>=3.
// Batched over blockIdx.z: (b,h) = (z/Hdiv, z%Hdiv).
// ---------------------------------------------------------------------------
template <int BM, int BN, int WM, int WN, int EPI, bool BTRANS, bool ENTA>
__global__ __launch_bounds__(256, 2)
void tgemm(const float* __restrict__ Ag, const float* __restrict__ Bg,
           const float* __restrict__ bias, float* __restrict__ Cg,
           const float* __restrict__ tau,
           int M, int N, int K, int lda, int ldb, int ldc,
           long long sA_b, long long sA_h,
           long long sB_b, long long sB_h,
           long long sC_b, long long sC_h, int Hdiv)
{
    constexpr int BK = 16;
    constexpr int WARPS_N = BN / WN;
    constexpr int MI = WM / 16;
    constexpr int NI = WN / 8;
    constexpr int ASTR = ASTRc;              // 20
    constexpr int BNP  = BN + 8;
    constexpr int BS_ELEMS = BTRANS ? BN * ASTR : BK * BNP;

    extern __shared__ __align__(16) float dsm[];
    float* AsBase = dsm;                          // STAGES * BM * ASTR
    float* BsBase = dsm + STAGES * BM * ASTR;     // STAGES * BS_ELEMS

    int z  = blockIdx.z;
    int bb = z / Hdiv, hh = z - bb * Hdiv;
    const float* A = Ag + (size_t)bb * sA_b + (size_t)hh * sA_h;
    const float* B = Bg + (size_t)bb * sB_b + (size_t)hh * sB_h;
    float*       C = Cg + (size_t)bb * sC_b + (size_t)hh * sC_h;

    const int tid  = threadIdx.x;
    const int lane = tid & 31;
    const int w    = tid >> 5;
    const int gid  = lane >> 2;   // 0..7
    const int tig  = lane & 3;    // 0..3
    const int wm0  = (w / WARPS_N) * WM;
    const int wn0  = (w % WARPS_N) * WN;
    const int m0   = blockIdx.y * BM;
    const int n0   = blockIdx.x * BN;

    // per-row -T for ENTA
    float nT[MI][2];
    if (ENTA) {
        const float* taup = tau + (size_t)z * Sn;
#pragma unroll
        for (int mi = 0; mi < MI; mi++) {
            nT[mi][0] = -taup[m0 + wm0 + mi * 16 + gid];
            nT[mi][1] = -taup[m0 + wm0 + mi * 16 + gid + 8];
        }
    }

    float acc[MI][NI][4];
#pragma unroll
    for (int i = 0; i < MI; i++)
#pragma unroll
        for (int j = 0; j < NI; j++)
#pragma unroll
            for (int c = 0; c < 4; c++) acc[i][j][c] = 0.f;

    const int nTiles = K / BK;

    auto load_tile = [&](int kt, int buf) {
        float* As = AsBase + buf * (BM * ASTR);
        float* Bs = BsBase + buf * BS_ELEMS;
#pragma unroll
        for (int i = tid; i < BM * 4; i += 256) {
            int m = i >> 2, kc = (i & 3) * 4;
            cpa16(&As[m * ASTR + kc], A + (size_t)(m0 + m) * lda + kt * BK + kc);
        }
        if (BTRANS) {
#pragma unroll
            for (int i = tid; i < BN * 4; i += 256) {
                int n = i >> 2, kc = (i & 3) * 4;
                cpa16(&Bs[n * ASTR + kc], B + (size_t)(n0 + n) * ldb + kt * BK + kc);
            }
        } else {
#pragma unroll
            for (int i = tid; i < BK * BN / 4; i += 256) {
                int kr = i / (BN / 4), nq = (i % (BN / 4)) * 4;
                cpa16(&Bs[kr * BNP + nq], B + (size_t)(kt * BK + kr) * ldb + n0 + nq);
            }
        }
        cp_commit();
    };

    load_tile(0, 0);
    load_tile(1, 1);
    load_tile(2, 2);

    for (int kt = 0; kt < nTiles; kt++) {
        // Wait until tile kt is resident (allow newer in-flight groups)
        if      (kt + 2 < nTiles) cp_wait<2>();
        else if (kt + 1 < nTiles) cp_wait<1>();
        else                      cp_wait<0>();
        __syncthreads();
        // Prefetch kt+3 into the buffer consumed at kt-1 (safe: sync above)
        if (kt + 3 < nTiles) load_tile(kt + 3, (kt + 3) & 3);

        int buf = kt & 3;
        const float* As = AsBase + buf * (BM * ASTR);
        const float* Bs = BsBase + buf * BS_ELEMS;

#pragma unroll
        for (int ks = 0; ks < BK; ks += 8) {
            uint32_t af[MI][4], bf[NI][2];
#pragma unroll
            for (int mi = 0; mi < MI; mi++) {
                const float* ap = As + (wm0 + mi * 16 + gid) * ASTR + ks + tig;
                if (ENTA) {
                    float p0 = fmaxf(fmaf(ap[0],            0.0625f, nT[mi][0]), 0.f);
                    float p1 = fmaxf(fmaf(ap[8 * ASTR],     0.0625f, nT[mi][1]), 0.f);
                    float p2 = fmaxf(fmaf(ap[4],            0.0625f, nT[mi][0]), 0.f);
                    float p3 = fmaxf(fmaf(ap[8 * ASTR + 4], 0.0625f, nT[mi][1]), 0.f);
                    af[mi][0] = __float_as_uint(to_tf32(p0 * p0));
                    af[mi][1] = __float_as_uint(to_tf32(p1 * p1));
                    af[mi][2] = __float_as_uint(to_tf32(p2 * p2));
                    af[mi][3] = __float_as_uint(to_tf32(p3 * p3));
                } else {
                    af[mi][0] = __float_as_uint(to_tf32(ap[0]));
                    af[mi][1] = __float_as_uint(to_tf32(ap[8 * ASTR]));
                    af[mi][2] = __float_as_uint(to_tf32(ap[4]));
                    af[mi][3] = __float_as_uint(to_tf32(ap[8 * ASTR + 4]));
                }
            }
#pragma unroll
            for (int ni = 0; ni < NI; ni++) {
                if (BTRANS) {
                    const float* bp = Bs + (wn0 + ni * 8 + gid) * ASTR + ks + tig;
                    bf[ni][0] = __float_as_uint(to_tf32(bp[0]));
                    bf[ni][1] = __float_as_uint(to_tf32(bp[4]));
                } else {
                    const float* bp = Bs + (ks + tig) * BNP + wn0 + ni * 8 + gid;
                    bf[ni][0] = __float_as_uint(to_tf32(bp[0]));
                    bf[ni][1] = __float_as_uint(to_tf32(bp[4 * BNP]));
                }
            }
#pragma unroll
            for (int mi = 0; mi < MI; mi++)
#pragma unroll
                for (int ni = 0; ni < NI; ni++) {
                    asm volatile(
                        "mma.sync.aligned.m16n8k8.row.col.f32.tf32.tf32.f32 "
                        "{%0,%1,%2,%3}, {%4,%5,%6,%7}, {%8,%9}, {%0,%1,%2,%3};"
                        : "+f"(acc[mi][ni][0]), "+f"(acc[mi][ni][1]),
                          "+f"(acc[mi][ni][2]), "+f"(acc[mi][ni][3])
                        : "r"(af[mi][0]), "r"(af[mi][1]),
                          "r"(af[mi][2]), "r"(af[mi][3]),
                          "r"(bf[ni][0]), "r"(bf[ni][1]));
                }
        }
    }

    // --- Epilogue ---
#pragma unroll
    for (int mi = 0; mi < MI; mi++) {
#pragma unroll
        for (int ni = 0; ni < NI; ni++) {
            int row = m0 + wm0 + mi * 16 + gid;
            int col = n0 + wn0 + ni * 8 + tig * 2;
            float b0 = 0.f, b1 = 0.f;
            if (EPI >= 1) { b0 = bias[col]; b1 = bias[col + 1]; }
            float v0 = acc[mi][ni][0] + b0, v1 = acc[mi][ni][1] + b1;
            float v2 = acc[mi][ni][2] + b0, v3 = acc[mi][ni][3] + b1;
            if (EPI == 2) { v0 = mish_f(v0); v1 = mish_f(v1); v2 = mish_f(v2); v3 = mish_f(v3); }
            *(float2*)(C + (size_t)row * ldc + col)       = make_float2(v0, v1);
            *(float2*)(C + (size_t)(row + 8) * ldc + col) = make_float2(v2, v3);
        }
    }
}

// ---------------------------------------------------------------------------
// Pack Wq|Wk|Wv -> gWcat [512][1536], biases -> gBcat [1536]
// ---------------------------------------------------------------------------
__global__ __launch_bounds__(256)
void concat_qkv(const float* __restrict__ Wq, const float* __restrict__ Wk,
                const float* __restrict__ Wv,
                const float* __restrict__ bq, const float* __restrict__ bk,
                const float* __restrict__ bv,
                float* __restrict__ Wcat, float* __restrict__ bcat)
{
    int i = blockIdx.x * 256 + threadIdx.x;
    if (i < Dn * Dn) {
        int k = i >> 9, n = i & 511;
        Wcat[k * D3 + n]          = Wq[i];
        Wcat[k * D3 + Dn + n]     = Wk[i];
        Wcat[k * D3 + 2 * Dn + n] = Wv[i];
    }
    if (i < Dn) {
        bcat[i]          = bq[i];
        bcat[Dn + i]     = bk[i];
        bcat[2 * Dn + i] = bv[i];
    }
}

// ---------------------------------------------------------------------------
// entmax-1.5 tau solve, warp-per-row. Reads raw scores; writes T = m + tau*.
// z = raw/16. After max-subtraction tau* lies in [-1, 0], so the support is a
// subset of {z > -1}. Compact those candidates (typically few) into smem and
// run the solver (5 bisect + 4 Newton + exact closed-form) on candidates only
// -- exact, since non-candidates contribute 0 to every sum for t >= -1.
// Full-array fallback if candidate count exceeds the cap.
// ---------------------------------------------------------------------------
__global__ __launch_bounds__(256)
void entmax_tau_kernel(const float* __restrict__ S, float* __restrict__ Tau)
{
    constexpr int CAP = 96;
    __shared__ float cand[8][CAP];
    __shared__ int   cnt[8];

    const int wrow = threadIdx.x >> 5;   // warp index = row within block
    const int row  = (blockIdx.x << 3) + wrow;
    const int lane = threadIdx.x & 31;
    const float4* r = (const float4*)(S + (size_t)row * 1024);

    float z[32];
#pragma unroll
    for (int wq = 0; wq < 8; wq++) {
        float4 v = r[wq * 32 + lane];
        z[wq * 4 + 0] = v.x * 0.0625f; z[wq * 4 + 1] = v.y * 0.0625f;
        z[wq * 4 + 2] = v.z * 0.0625f; z[wq * 4 + 3] = v.w * 0.0625f;
    }

    float m = z[0];
#pragma unroll
    for (int j = 1; j < 32; j++) m = fmaxf(m, z[j]);
#pragma unroll
    for (int o = 16; o > 0; o >>= 1) m = fmaxf(m, __shfl_xor_sync(0xffffffffu, m, o));
#pragma unroll
    for (int j = 0; j < 32; j++) z[j] -= m;

    if (lane == 0) cnt[wrow] = 0;
    __syncwarp();
#pragma unroll
    for (int j = 0; j < 32; j++) {
        if (z[j] > -1.f) {
            int p = atomicAdd(&cnt[wrow], 1);
            if (p < CAP) cand[wrow][p] = z[j];
        }
    }
    __syncwarp();
    const int total = cnt[wrow];

    float tau;
    if (total <= CAP) {
        // ---- candidate-only solver (<=3 elems per lane) ----
        float c0 = (lane      < total) ? cand[wrow][lane]      : -2.f;
        float c1 = (lane + 32 < total) ? cand[wrow][lane + 32] : -2.f;
        float c2 = (lane + 64 < total) ? cand[wrow][lane + 64] : -2.f;

        float lo = -1.f, hi = 0.f;
#pragma unroll
        for (int it = 0; it < 5; it++) {
            float mid = 0.5f * (lo + hi);
            float d0 = fmaxf(c0 - mid, 0.f);
            float d1 = fmaxf(c1 - mid, 0.f);
            float d2 = fmaxf(c2 - mid, 0.f);
            float s = d0 * d0 + d1 * d1 + d2 * d2;
#pragma unroll
            for (int o = 16; o > 0; o >>= 1) s += __shfl_xor_sync(0xffffffffu, s, o);
            if (s > 1.f) lo = mid; else hi = mid;
        }

        float t = lo;
#pragma unroll
        for (int it = 0; it < 4; it++) {
            float d0 = fmaxf(c0 - t, 0.f);
            float d1 = fmaxf(c1 - t, 0.f);
            float d2 = fmaxf(c2 - t, 0.f);
            float s1 = d0 + d1 + d2;
            float s2 = d0 * d0 + d1 * d1 + d2 * d2;
#pragma unroll
            for (int o = 16; o > 0; o >>= 1) {
                s1 += __shfl_xor_sync(0xffffffffu, s1, o);
                s2 += __shfl_xor_sync(0xffffffffu, s2, o);
            }
            t += (s2 - 1.f) / (2.f * s1);
        }

        float c = 0.f, s1 = 0.f, s2 = 0.f;
        if (c0 > t) { c += 1.f; s1 += c0; s2 = fmaf(c0, c0, s2); }
        if (c1 > t) { c += 1.f; s1 += c1; s2 = fmaf(c1, c1, s2); }
        if (c2 > t) { c += 1.f; s1 += c2; s2 = fmaf(c2, c2, s2); }
#pragma unroll
        for (int o = 16; o > 0; o >>= 1) {
            c  += __shfl_xor_sync(0xffffffffu, c,  o);
            s1 += __shfl_xor_sync(0xffffffffu, s1, o);
            s2 += __shfl_xor_sync(0xffffffffu, s2, o);
        }
        float disc = fmaxf(s1 * s1 - c * (s2 - 1.f), 0.f);
        tau = (s1 - sqrtf(disc)) / c;
    } else {
        // ---- full-array fallback ----
        float lo = -1.f, hi = 0.f;
#pragma unroll
        for (int it = 0; it < 5; it++) {
            float mid = 0.5f * (lo + hi);
            float s = 0.f;
#pragma unroll
            for (int j = 0; j < 32; j++) {
                float d = fmaxf(z[j] - mid, 0.f);
                s = fmaf(d, d, s);
            }
#pragma unroll
            for (int o = 16; o > 0; o >>= 1) s += __shfl_xor_sync(0xffffffffu, s, o);
            if (s > 1.f) lo = mid; else hi = mid;
        }
        float t = lo;
#pragma unroll
        for (int it = 0; it < 4; it++) {
            float s1 = 0.f, s2 = 0.f;
#pragma unroll
            for (int j = 0; j < 32; j++) {
                float d = fmaxf(z[j] - t, 0.f);
                s1 += d;
                s2 = fmaf(d, d, s2);
            }
#pragma unroll
            for (int o = 16; o > 0; o >>= 1) {
                s1 += __shfl_xor_sync(0xffffffffu, s1, o);
                s2 += __shfl_xor_sync(0xffffffffu, s2, o);
            }
            t += (s2 - 1.f) / (2.f * s1);
        }
        float c = 0.f, s1 = 0.f, s2 = 0.f;
#pragma unroll
        for (int j = 0; j < 32; j++) {
            if (z[j] > t) { c += 1.f; s1 += z[j]; s2 = fmaf(z[j], z[j], s2); }
        }
#pragma unroll
        for (int o = 16; o > 0; o >>= 1) {
            c  += __shfl_xor_sync(0xffffffffu, c,  o);
            s1 += __shfl_xor_sync(0xffffffffu, s1, o);
            s2 += __shfl_xor_sync(0xffffffffu, s2, o);
        }
        float disc = fmaxf(s1 * s1 - c * (s2 - 1.f), 0.f);
        tau = (s1 - sqrtf(disc)) / c;
    }

    if (lane == 0) Tau[row] = m + tau;
}

// ---------------------------------------------------------------------------
__device__ __forceinline__ float blkRedSum(float v, float* sm) {
#pragma unroll
    for (int o = 16; o > 0; o >>= 1) v += __shfl_xor_sync(0xffffffffu, v, o);
    int nw = blockDim.x >> 5;
    if ((threadIdx.x & 31) == 0) sm[threadIdx.x >> 5] = v;
    __syncthreads();
    if (threadIdx.x == 0) {
        float s = sm[0];
        for (int i = 1; i < nw; i++) s += sm[i];
        sm[0] = s;
    }
    __syncthreads();
    float r = sm[0];
    __syncthreads();
    return r;
}

// out = residual + LayerNorm(y) * g + b   (rows of 512, eps=1e-5, biased var)
__global__ __launch_bounds__(128)
void add_ln_kernel(const float* __restrict__ Y, const float* __restrict__ R,
                   const float* __restrict__ g, const float* __restrict__ b,
                   float* __restrict__ O)
{
    __shared__ float sm[4];
    size_t row = blockIdx.x;
    const float* y = Y + row * 512;
    int tid = threadIdx.x;

    float v[4];
#pragma unroll
    for (int j = 0; j < 4; j++) v[j] = y[tid + j * 128];
    float s = 0.f, ss = 0.f;
#pragma unroll
    for (int j = 0; j < 4; j++) { s += v[j]; ss = fmaf(v[j], v[j], ss); }
    s  = blkRedSum(s,  sm);
    ss = blkRedSum(ss, sm);
    float mean = s * (1.f / 512.f);
    float var  = ss * (1.f / 512.f) - mean * mean;
    float rstd = rsqrtf(var + 1e-5f);
#pragma unroll
    for (int j = 0; j < 4; j++) {
        int c = tid + j * 128;
        O[row * 512 + c] = R[row * 512 + c] + (v[j] - mean) * rstd * g[c] + b[c];
    }
}

// ---------------------------------------------------------------------------
extern "C" void kernel_launch(void* const* d_in, const int* in_sizes, int n_in,
                              void* d_out, int out_size)
{
    const float* x   = (const float*)d_in[0];
    const float* Wq  = (const float*)d_in[1];  const float* bq  = (const float*)d_in[2];
    const float* Wk  = (const float*)d_in[3];  const float* bk  = (const float*)d_in[4];
    const float* Wv  = (const float*)d_in[5];  const float* bv  = (const float*)d_in[6];
    const float* Wo  = (const float*)d_in[7];  const float* bo  = (const float*)d_in[8];
    const float* g1  = (const float*)d_in[9];  const float* be1 = (const float*)d_in[10];
    const float* W1  = (const float*)d_in[11]; const float* b1  = (const float*)d_in[12];
    const float* W2  = (const float*)d_in[13]; const float* b2  = (const float*)d_in[14];
    const float* g2  = (const float*)d_in[15]; const float* be2 = (const float*)d_in[16];
    float* out = (float*)d_out;

    float *qkv, *wcat, *bcat, *s, *taub, *ctx, *y, *x1, *h1, *y2;
    cudaGetSymbolAddress((void**)&qkv,  gQKV);
    cudaGetSymbolAddress((void**)&wcat, gWcat);
    cudaGetSymbolAddress((void**)&bcat, gBcat);
    cudaGetSymbolAddress((void**)&s,    gS);
    cudaGetSymbolAddress((void**)&taub, gTau);
    cudaGetSymbolAddress((void**)&ctx,  gCtx);
    cudaGetSymbolAddress((void**)&y,    gY);
    cudaGetSymbolAddress((void**)&x1,   gX1);
    cudaGetSymbolAddress((void**)&h1,   gH1);
    cudaGetSymbolAddress((void**)&y2,   gY2);

    const long long SD3 = (long long)Sn * D3;
    const long long SS  = (long long)Sn * Sn;
    const long long SD  = (long long)Sn * Dn;

    // Opt in to >48KB dynamic smem for each instantiation
    constexpr size_t SM_BIG  = tg_smem_bytes(128, 128, false);
    constexpr size_t SM_BIGT = tg_smem_bytes(128, 128, true);
    constexpr size_t SM_ATT  = tg_smem_bytes(128, 64,  false);
    cudaFuncSetAttribute((const void*)tgemm<128,128,64,32,EPI_BIAS,false,false>,
                         cudaFuncAttributeMaxDynamicSharedMemorySize, (int)SM_BIG);
    cudaFuncSetAttribute((const void*)tgemm<128,128,64,32,EPI_NONE,true,false>,
                         cudaFuncAttributeMaxDynamicSharedMemorySize, (int)SM_BIGT);
    cudaFuncSetAttribute((const void*)tgemm<128,64,32,32,EPI_NONE,false,true>,
                         cudaFuncAttributeMaxDynamicSharedMemorySize, (int)SM_ATT);
    cudaFuncSetAttribute((const void*)tgemm<128,128,64,32,EPI_MISH,false,false>,
                         cudaFuncAttributeMaxDynamicSharedMemorySize, (int)SM_BIG);

    // 0) pack QKV weights/biases
    concat_qkv<<<(Dn * Dn + 255) / 256, 256>>>(Wq, Wk, Wv, bq, bk, bv, wcat, bcat);

    // 1) QKV in one GEMM: [8192,512] @ [512,1536] + bias -> gQKV
    tgemm<128,128,64,32,EPI_BIAS,false,false>
        <<<dim3(D3 / 128, Mtok / 128, 1), 256, SM_BIG>>>(
        x, wcat, bcat, qkv, nullptr, Mtok, D3, Dn, Dn, D3, D3, 0,0,0,0,0,0, 1);

    // 2) scores[b,h] = Q_h @ K_h^T (NT, K=64), batched over 64 (b,h)
    tgemm<128,128,64,32,EPI_NONE,true,false>
        <<<dim3(Sn / 128, Sn / 128, Bn * Hn), 256, SM_BIGT>>>(
        qkv, qkv + Dn, nullptr, s, nullptr, Sn, Sn, HD, D3, D3, Sn,
        SD3, HD, SD3, HD, (long long)Hn * SS, SS, Hn);

    // 3) entmax-1.5 tau per score row -> gTau (candidate-compacted solver)
    entmax_tau_kernel<<<Bn * Hn * Sn / 8, 256>>>(s, taub);

    // 4) ctx_h = entmax(scores) @ V_h with fused apply (NN, M=1024, N=64, K=1024)
    tgemm<128,64,32,32,EPI_NONE,false,true>
        <<<dim3(1, Sn / 128, Bn * Hn), 256, SM_ATT>>>(
        s, qkv + 2 * Dn, nullptr, ctx, taub, Sn, HD, Sn, Sn, D3, Dn,
        (long long)Hn * SS, SS, SD3, HD, SD, HD, Hn);

    // 5) y = ctx @ Wo + bo
    tgemm<128,128,64,32,EPI_BIAS,false,false>
        <<<dim3(Dn / 128, Mtok / 128, 1), 256, SM_BIG>>>(
        ctx, Wo, bo, y, nullptr, Mtok, Dn, Dn, Dn, Dn, Dn, 0,0,0,0,0,0, 1);

    // 6) x1 = x + LN(y)
    add_ln_kernel<<<Mtok, 128>>>(y, x, g1, be1, x1);

    // 7) h1 = mish(x1 @ W1 + b1)  [8192,2048]
    tgemm<128,128,64,32,EPI_MISH,false,false>
        <<<dim3(Fn / 128, Mtok / 128, 1), 256, SM_BIG>>>(
        x1, W1, b1, h1, nullptr, Mtok, Fn, Dn, Dn, Fn, Fn, 0,0,0,0,0,0, 1);

    // 8) y2 = h1 @ W2 + b2  [8192,512]
    tgemm<128,128,64,32,EPI_BIAS,false,false>
        <<<dim3(Dn / 128, Mtok / 128, 1), 256, SM_BIG>>>(
        h1, W2, b2, y2, nullptr, Mtok, Dn, Fn, Fn, Dn, Dn, 0,0,0,0,0,0, 1);

    // 9) out = x1 + LN(y2)
    add_ln_kernel<<<Mtok, 128>>>(y2, x1, g2, be2, out);
}

// round 7
// speedup vs baseline: 1.1944x; 1.0903x over previous
#include <cuda_runtime.h>
#include <math.h>
#include <stdint.h>

// Problem constants
constexpr int Bn = 8, Sn = 1024, Dn = 512, Hn = 8, HD = 64, Fn = 2048;
constexpr int Mtok = Bn * Sn; // 8192
constexpr int D3 = 3 * Dn;    // 1536

// Scratch (static device globals; no runtime allocation)
__device__ float gQKV [(size_t)Mtok * D3];          // packed Q|K|V rows
__device__ float gWcat[Dn * D3];
__device__ float gBcat[D3];
__device__ float gS  [(size_t)Bn * Hn * Sn * Sn];   // 256 MB raw scores
__device__ float gTau[Bn * Hn * Sn];                // per-row threshold (scaled)
__device__ float gCtx[Mtok * Dn];
__device__ float gY  [Mtok * Dn];
__device__ float gX1 [Mtok * Dn];
__device__ float gH1 [(size_t)Mtok * Fn];
__device__ float gY2 [Mtok * Dn];

enum { EPI_NONE = 0, EPI_BIAS = 1, EPI_MISH = 2 };

// mish(x) = x*tanh(softplus(x)); with t=e^x, tanh(ln(1+t)) = (t^2+2t)/(t^2+2t+2)
__device__ __forceinline__ float mish_f(float v) {
    if (v > 20.f) return v;
    float t = __expf(v);
    float u = fmaf(t, t, 2.f * t);
    return v * u / (u + 2.f);
}

__device__ __forceinline__ float to_tf32(float x) {
    float r;
    asm("cvt.rna.tf32.f32 %0, %1;" : "=f"(r) : "f"(x));
    return r;
}

__device__ __forceinline__ void cpa16(float* smem_dst, const float* gsrc) {
    uint32_t a = (uint32_t)__cvta_generic_to_shared(smem_dst);
    asm volatile("cp.async.cg.shared.global [%0], [%1], 16;" :: "r"(a), "l"(gsrc));
}
__device__ __forceinline__ void cp_commit() {
    asm volatile("cp.async.commit_group;");
}
template <int NN>
__device__ __forceinline__ void cp_wait() {
    asm volatile("cp.async.wait_group %0;" :: "n"(NN));
}

// Host/device-consistent smem sizing (3-stage pipeline)
constexpr int ASTRc = 20;
constexpr size_t tg_smem_bytes(int BM, int BN, bool BT) {
    int bs = BT ? BN * ASTRc : 16 * (BN + 8);
    return (size_t)(BM * ASTRc + bs) * 3 * sizeof(float);
}

// ---------------------------------------------------------------------------
// tf32 tensor-core GEMM, 3-stage cp.async pipeline: C = A @ B (+bias)(+mish).
// BTRANS: B stored [N,K] (K contiguous) -> C = A @ B^T.
// ENTA:   A element transform p = (max(a*0.0625 - T[row], 0))^2 at fragment
//         load (entmax apply fused into attn@V).
// ---------------------------------------------------------------------------
template <int BM, int BN, int WM, int WN, int EPI, bool BTRANS, bool ENTA>
__global__ __launch_bounds__(256, 2)
void tgemm(const float* __restrict__ Ag, const float* __restrict__ Bg,
           const float* __restrict__ bias, float* __restrict__ Cg,
           const float* __restrict__ tau,
           int M, int N, int K, int lda, int ldb, int ldc,
           long long sA_b, long long sA_h,
           long long sB_b, long long sB_h,
           long long sC_b, long long sC_h, int Hdiv)
{
    constexpr int BK = 16;
    constexpr int WARPS_N = BN / WN;
    constexpr int MI = WM / 16;
    constexpr int NI = WN / 8;
    constexpr int ASTR = ASTRc;              // 20
    constexpr int BNP  = BN + 8;
    constexpr int BS_ELEMS = BTRANS ? BN * ASTR : BK * BNP;

    extern __shared__ __align__(16) float dsm[];
    float* AsBase = dsm;                          // 3 * BM * ASTR
    float* BsBase = dsm + 3 * BM * ASTR;          // 3 * BS_ELEMS

    int z  = blockIdx.z;
    int bb = z / Hdiv, hh = z - bb * Hdiv;
    const float* A = Ag + (size_t)bb * sA_b + (size_t)hh * sA_h;
    const float* B = Bg + (size_t)bb * sB_b + (size_t)hh * sB_h;
    float*       C = Cg + (size_t)bb * sC_b + (size_t)hh * sC_h;

    const int tid  = threadIdx.x;
    const int lane = tid & 31;
    const int w    = tid >> 5;
    const int gid  = lane >> 2;   // 0..7
    const int tig  = lane & 3;    // 0..3
    const int wm0  = (w / WARPS_N) * WM;
    const int wn0  = (w % WARPS_N) * WN;
    const int m0   = blockIdx.y * BM;
    const int n0   = blockIdx.x * BN;

    // per-row -T for ENTA
    float nT[MI][2];
    if (ENTA) {
        const float* taup = tau + (size_t)z * Sn;
#pragma unroll
        for (int mi = 0; mi < MI; mi++) {
            nT[mi][0] = -taup[m0 + wm0 + mi * 16 + gid];
            nT[mi][1] = -taup[m0 + wm0 + mi * 16 + gid + 8];
        }
    }

    float acc[MI][NI][4];
#pragma unroll
    for (int i = 0; i < MI; i++)
#pragma unroll
        for (int j = 0; j < NI; j++)
#pragma unroll
            for (int c = 0; c < 4; c++) acc[i][j][c] = 0.f;

    const int nTiles = K / BK;

    auto load_tile = [&](int kt, int buf) {
        float* As = AsBase + buf * (BM * ASTR);
        float* Bs = BsBase + buf * BS_ELEMS;
#pragma unroll
        for (int i = tid; i < BM * 4; i += 256) {
            int m = i >> 2, kc = (i & 3) * 4;
            cpa16(&As[m * ASTR + kc], A + (size_t)(m0 + m) * lda + kt * BK + kc);
        }
        if (BTRANS) {
#pragma unroll
            for (int i = tid; i < BN * 4; i += 256) {
                int n = i >> 2, kc = (i & 3) * 4;
                cpa16(&Bs[n * ASTR + kc], B + (size_t)(n0 + n) * ldb + kt * BK + kc);
            }
        } else {
#pragma unroll
            for (int i = tid; i < BK * BN / 4; i += 256) {
                int kr = i / (BN / 4), nq = (i % (BN / 4)) * 4;
                cpa16(&Bs[kr * BNP + nq], B + (size_t)(kt * BK + kr) * ldb + n0 + nq);
            }
        }
        cp_commit();
    };

    load_tile(0, 0);
    load_tile(1, 1);

    for (int kt = 0; kt < nTiles; kt++) {
        if (kt + 1 >= nTiles) cp_wait<0>(); else cp_wait<1>();
        __syncthreads();
        if (kt + 2 < nTiles) load_tile(kt + 2, (kt + 2) % 3);

        int buf = kt % 3;
        const float* As = AsBase + buf * (BM * ASTR);
        const float* Bs = BsBase + buf * BS_ELEMS;

#pragma unroll
        for (int ks = 0; ks < BK; ks += 8) {
            uint32_t af[MI][4], bf[NI][2];
#pragma unroll
            for (int mi = 0; mi < MI; mi++) {
                const float* ap = As + (wm0 + mi * 16 + gid) * ASTR + ks + tig;
                if (ENTA) {
                    float p0 = fmaxf(fmaf(ap[0],            0.0625f, nT[mi][0]), 0.f);
                    float p1 = fmaxf(fmaf(ap[8 * ASTR],     0.0625f, nT[mi][1]), 0.f);
                    float p2 = fmaxf(fmaf(ap[4],            0.0625f, nT[mi][0]), 0.f);
                    float p3 = fmaxf(fmaf(ap[8 * ASTR + 4], 0.0625f, nT[mi][1]), 0.f);
                    af[mi][0] = __float_as_uint(to_tf32(p0 * p0));
                    af[mi][1] = __float_as_uint(to_tf32(p1 * p1));
                    af[mi][2] = __float_as_uint(to_tf32(p2 * p2));
                    af[mi][3] = __float_as_uint(to_tf32(p3 * p3));
                } else {
                    af[mi][0] = __float_as_uint(to_tf32(ap[0]));
                    af[mi][1] = __float_as_uint(to_tf32(ap[8 * ASTR]));
                    af[mi][2] = __float_as_uint(to_tf32(ap[4]));
                    af[mi][3] = __float_as_uint(to_tf32(ap[8 * ASTR + 4]));
                }
            }
#pragma unroll
            for (int ni = 0; ni < NI; ni++) {
                if (BTRANS) {
                    const float* bp = Bs + (wn0 + ni * 8 + gid) * ASTR + ks + tig;
                    bf[ni][0] = __float_as_uint(to_tf32(bp[0]));
                    bf[ni][1] = __float_as_uint(to_tf32(bp[4]));
                } else {
                    const float* bp = Bs + (ks + tig) * BNP + wn0 + ni * 8 + gid;
                    bf[ni][0] = __float_as_uint(to_tf32(bp[0]));
                    bf[ni][1] = __float_as_uint(to_tf32(bp[4 * BNP]));
                }
            }
#pragma unroll
            for (int mi = 0; mi < MI; mi++)
#pragma unroll
                for (int ni = 0; ni < NI; ni++) {
                    asm volatile(
                        "mma.sync.aligned.m16n8k8.row.col.f32.tf32.tf32.f32 "
                        "{%0,%1,%2,%3}, {%4,%5,%6,%7}, {%8,%9}, {%0,%1,%2,%3};"
                        : "+f"(acc[mi][ni][0]), "+f"(acc[mi][ni][1]),
                          "+f"(acc[mi][ni][2]), "+f"(acc[mi][ni][3])
                        : "r"(af[mi][0]), "r"(af[mi][1]),
                          "r"(af[mi][2]), "r"(af[mi][3]),
                          "r"(bf[ni][0]), "r"(bf[ni][1]));
                }
        }
    }

    // --- Epilogue ---
#pragma unroll
    for (int mi = 0; mi < MI; mi++) {
#pragma unroll
        for (int ni = 0; ni < NI; ni++) {
            int row = m0 + wm0 + mi * 16 + gid;
            int col = n0 + wn0 + ni * 8 + tig * 2;
            float b0 = 0.f, b1 = 0.f;
            if (EPI >= 1) { b0 = bias[col]; b1 = bias[col + 1]; }
            float v0 = acc[mi][ni][0] + b0, v1 = acc[mi][ni][1] + b1;
            float v2 = acc[mi][ni][2] + b0, v3 = acc[mi][ni][3] + b1;
            if (EPI == 2) { v0 = mish_f(v0); v1 = mish_f(v1); v2 = mish_f(v2); v3 = mish_f(v3); }
            *(float2*)(C + (size_t)row * ldc + col)       = make_float2(v0, v1);
            *(float2*)(C + (size_t)(row + 8) * ldc + col) = make_float2(v2, v3);
        }
    }
}

// ---------------------------------------------------------------------------
// Pack Wq|Wk|Wv -> gWcat [512][1536], biases -> gBcat [1536]
// ---------------------------------------------------------------------------
__global__ __launch_bounds__(256)
void concat_qkv(const float* __restrict__ Wq, const float* __restrict__ Wk,
                const float* __restrict__ Wv,
                const float* __restrict__ bq, const float* __restrict__ bk,
                const float* __restrict__ bv,
                float* __restrict__ Wcat, float* __restrict__ bcat)
{
    int i = blockIdx.x * 256 + threadIdx.x;
    if (i < Dn * Dn) {
        int k = i >> 9, n = i & 511;
        Wcat[k * D3 + n]          = Wq[i];
        Wcat[k * D3 + Dn + n]     = Wk[i];
        Wcat[k * D3 + 2 * Dn + n] = Wv[i];
    }
    if (i < Dn) {
        bcat[i]          = bq[i];
        bcat[Dn + i]     = bk[i];
        bcat[2 * Dn + i] = bv[i];
    }
}

// ---------------------------------------------------------------------------
// entmax-1.5 tau solve in the RAW score domain, warp-per-row.
// z = raw/16; solving sum((raw - T)+^2) = 256 over raw values is equivalent
// (T = 16*(m+tau)); bracket [Ymax-16, Ymax]. 3 bisect + 3 Newton (Newton from
// the left bracket of a convex decreasing f stays left, monotone) + exact
// closed-form on the identified support. Stores T*0.0625 for the fused apply.
// ---------------------------------------------------------------------------
__global__ __launch_bounds__(256)
void entmax_tau_kernel(const float* __restrict__ S, float* __restrict__ Tau)
{
    int row  = (blockIdx.x << 3) + (threadIdx.x >> 5);
    int lane = threadIdx.x & 31;
    const float4* r = (const float4*)(S + (size_t)row * 1024);

    float y[32];
#pragma unroll
    for (int wq = 0; wq < 8; wq++) {
        float4 v = r[wq * 32 + lane];
        y[wq * 4 + 0] = v.x; y[wq * 4 + 1] = v.y;
        y[wq * 4 + 2] = v.z; y[wq * 4 + 3] = v.w;
    }

    float m = y[0];
#pragma unroll
    for (int j = 1; j < 32; j++) m = fmaxf(m, y[j]);
#pragma unroll
    for (int o = 16; o > 0; o >>= 1) m = fmaxf(m, __shfl_xor_sync(0xffffffffu, m, o));

    // Bisection: T* in [m-16, m], f(lo) >= 256 invariant
    float lo = m - 16.f, hi = m;
#pragma unroll
    for (int it = 0; it < 3; it++) {
        float mid = 0.5f * (lo + hi);
        float sa = 0.f, sb = 0.f;
#pragma unroll
        for (int j = 0; j < 32; j += 2) {
            float d0 = fmaxf(y[j]     - mid, 0.f);
            float d1 = fmaxf(y[j + 1] - mid, 0.f);
            sa = fmaf(d0, d0, sa);
            sb = fmaf(d1, d1, sb);
        }
        float s = sa + sb;
#pragma unroll
        for (int o = 16; o > 0; o >>= 1) s += __shfl_xor_sync(0xffffffffu, s, o);
        if (s > 256.f) lo = mid; else hi = mid;
    }

    // Newton from the left bracket: t <- t + (f-256)/(2*S1)
    float t = lo;
#pragma unroll
    for (int it = 0; it < 3; it++) {
        float s1 = 0.f, s2a = 0.f, s2b = 0.f;
#pragma unroll
        for (int j = 0; j < 32; j += 2) {
            float d0 = fmaxf(y[j]     - t, 0.f);
            float d1 = fmaxf(y[j + 1] - t, 0.f);
            s1 += d0 + d1;
            s2a = fmaf(d0, d0, s2a);
            s2b = fmaf(d1, d1, s2b);
        }
        float s2 = s2a + s2b;
#pragma unroll
        for (int o = 16; o > 0; o >>= 1) {
            s1 += __shfl_xor_sync(0xffffffffu, s1, o);
            s2 += __shfl_xor_sync(0xffffffffu, s2, o);
        }
        t += (s2 - 256.f) / (2.f * s1);
    }

    // Exact closed-form on support {y > t} (t <= T*):
    // T* = (S1 - sqrt(S1^2 - k(S2-256)))/k
    float c = 0.f, s1 = 0.f, s2 = 0.f;
#pragma unroll
    for (int j = 0; j < 32; j++) {
        if (y[j] > t) { c += 1.f; s1 += y[j]; s2 = fmaf(y[j], y[j], s2); }
    }
#pragma unroll
    for (int o = 16; o > 0; o >>= 1) {
        c  += __shfl_xor_sync(0xffffffffu, c,  o);
        s1 += __shfl_xor_sync(0xffffffffu, s1, o);
        s2 += __shfl_xor_sync(0xffffffffu, s2, o);
    }
    float disc = fmaxf(s1 * s1 - c * (s2 - 256.f), 0.f);
    float T    = (s1 - sqrtf(disc)) / c;

    if (lane == 0) Tau[row] = T * 0.0625f;
}

// ---------------------------------------------------------------------------
__device__ __forceinline__ float blkRedSum(float v, float* sm) {
#pragma unroll
    for (int o = 16; o > 0; o >>= 1) v += __shfl_xor_sync(0xffffffffu, v, o);
    int nw = blockDim.x >> 5;
    if ((threadIdx.x & 31) == 0) sm[threadIdx.x >> 5] = v;
    __syncthreads();
    if (threadIdx.x == 0) {
        float s = sm[0];
        for (int i = 1; i < nw; i++) s += sm[i];
        sm[0] = s;
    }
    __syncthreads();
    float r = sm[0];
    __syncthreads();
    return r;
}

// out = residual + LayerNorm(y) * g + b   (rows of 512, eps=1e-5, biased var)
__global__ __launch_bounds__(128)
void add_ln_kernel(const float* __restrict__ Y, const float* __restrict__ R,
                   const float* __restrict__ g, const float* __restrict__ b,
                   float* __restrict__ O)
{
    __shared__ float sm[4];
    size_t row = blockIdx.x;
    const float* y = Y + row * 512;
    int tid = threadIdx.x;

    float v[4];
#pragma unroll
    for (int j = 0; j < 4; j++) v[j] = y[tid + j * 128];
    float s = 0.f, ss = 0.f;
#pragma unroll
    for (int j = 0; j < 4; j++) { s += v[j]; ss = fmaf(v[j], v[j], ss); }
    s  = blkRedSum(s,  sm);
    ss = blkRedSum(ss, sm);
    float mean = s * (1.f / 512.f);
    float var  = ss * (1.f / 512.f) - mean * mean;
    float rstd = rsqrtf(var + 1e-5f);
#pragma unroll
    for (int j = 0; j < 4; j++) {
        int c = tid + j * 128;
        O[row * 512 + c] = R[row * 512 + c] + (v[j] - mean) * rstd * g[c] + b[c];
    }
}

// ---------------------------------------------------------------------------
extern "C" void kernel_launch(void* const* d_in, const int* in_sizes, int n_in,
                              void* d_out, int out_size)
{
    const float* x   = (const float*)d_in[0];
    const float* Wq  = (const float*)d_in[1];  const float* bq  = (const float*)d_in[2];
    const float* Wk  = (const float*)d_in[3];  const float* bk  = (const float*)d_in[4];
    const float* Wv  = (const float*)d_in[5];  const float* bv  = (const float*)d_in[6];
    const float* Wo  = (const float*)d_in[7];  const float* bo  = (const float*)d_in[8];
    const float* g1  = (const float*)d_in[9];  const float* be1 = (const float*)d_in[10];
    const float* W1  = (const float*)d_in[11]; const float* b1  = (const float*)d_in[12];
    const float* W2  = (const float*)d_in[13]; const float* b2  = (const float*)d_in[14];
    const float* g2  = (const float*)d_in[15]; const float* be2 = (const float*)d_in[16];
    float* out = (float*)d_out;

    float *qkv, *wcat, *bcat, *s, *taub, *ctx, *y, *x1, *h1, *y2;
    cudaGetSymbolAddress((void**)&qkv,  gQKV);
    cudaGetSymbolAddress((void**)&wcat, gWcat);
    cudaGetSymbolAddress((void**)&bcat, gBcat);
    cudaGetSymbolAddress((void**)&s,    gS);
    cudaGetSymbolAddress((void**)&taub, gTau);
    cudaGetSymbolAddress((void**)&ctx,  gCtx);
    cudaGetSymbolAddress((void**)&y,    gY);
    cudaGetSymbolAddress((void**)&x1,   gX1);
    cudaGetSymbolAddress((void**)&h1,   gH1);
    cudaGetSymbolAddress((void**)&y2,   gY2);

    const long long SD3 = (long long)Sn * D3;
    const long long SS  = (long long)Sn * Sn;
    const long long SD  = (long long)Sn * Dn;

    // Opt in to >48KB dynamic smem for each instantiation
    constexpr size_t SM_BIG  = tg_smem_bytes(128, 128, false);
    constexpr size_t SM_BIGT = tg_smem_bytes(128, 128, true);
    constexpr size_t SM_ATT  = tg_smem_bytes(64,  64,  false);
    cudaFuncSetAttribute((const void*)tgemm<128,128,64,32,EPI_BIAS,false,false>,
                         cudaFuncAttributeMaxDynamicSharedMemorySize, (int)SM_BIG);
    cudaFuncSetAttribute((const void*)tgemm<128,128,64,32,EPI_NONE,true,false>,
                         cudaFuncAttributeMaxDynamicSharedMemorySize, (int)SM_BIGT);
    cudaFuncSetAttribute((const void*)tgemm<64,64,32,16,EPI_NONE,false,true>,
                         cudaFuncAttributeMaxDynamicSharedMemorySize, (int)SM_ATT);
    cudaFuncSetAttribute((const void*)tgemm<128,128,64,32,EPI_MISH,false,false>,
                         cudaFuncAttributeMaxDynamicSharedMemorySize, (int)SM_BIG);

    // 0) pack QKV weights/biases
    concat_qkv<<<(Dn * Dn + 255) / 256, 256>>>(Wq, Wk, Wv, bq, bk, bv, wcat, bcat);

    // 1) QKV in one GEMM: [8192,512] @ [512,1536] + bias -> gQKV
    tgemm<128,128,64,32,EPI_BIAS,false,false>
        <<<dim3(D3 / 128, Mtok / 128, 1), 256, SM_BIG>>>(
        x, wcat, bcat, qkv, nullptr, Mtok, D3, Dn, Dn, D3, D3, 0,0,0,0,0,0, 1);

    // 2) scores[b,h] = Q_h @ K_h^T (NT, K=64), batched over 64 (b,h)
    tgemm<128,128,64,32,EPI_NONE,true,false>
        <<<dim3(Sn / 128, Sn / 128, Bn * Hn), 256, SM_BIGT>>>(
        qkv, qkv + Dn, nullptr, s, nullptr, Sn, Sn, HD, D3, D3, Sn,
        SD3, HD, SD3, HD, (long long)Hn * SS, SS, Hn);

    // 3) entmax-1.5 tau per score row -> gTau (raw-domain, 7-pass solver)
    entmax_tau_kernel<<<Bn * Hn * Sn / 8, 256>>>(s, taub);

    // 4) ctx_h = entmax(scores) @ V_h with fused apply (NN, M=1024, N=64, K=1024)
    tgemm<64,64,32,16,EPI_NONE,false,true>
        <<<dim3(1, Sn / 64, Bn * Hn), 256, SM_ATT>>>(
        s, qkv + 2 * Dn, nullptr, ctx, taub, Sn, HD, Sn, Sn, D3, Dn,
        (long long)Hn * SS, SS, SD3, HD, SD, HD, Hn);

    // 5) y = ctx @ Wo + bo
    tgemm<128,128,64,32,EPI_BIAS,false,false>
        <<<dim3(Dn / 128, Mtok / 128, 1), 256, SM_BIG>>>(
        ctx, Wo, bo, y, nullptr, Mtok, Dn, Dn, Dn, Dn, Dn, 0,0,0,0,0,0, 1);

    // 6) x1 = x + LN(y)
    add_ln_kernel<<<Mtok, 128>>>(y, x, g1, be1, x1);

    // 7) h1 = mish(x1 @ W1 + b1)  [8192,2048]
    tgemm<128,128,64,32,EPI_MISH,false,false>
        <<<dim3(Fn / 128, Mtok / 128, 1), 256, SM_BIG>>>(
        x1, W1, b1, h1, nullptr, Mtok, Fn, Dn, Dn, Fn, Fn, 0,0,0,0,0,0, 1);

    // 8) y2 = h1 @ W2 + b2  [8192,512]
    tgemm<128,128,64,32,EPI_BIAS,false,false>
        <<<dim3(Dn / 128, Mtok / 128, 1), 256, SM_BIG>>>(
        h1, W2, b2, y2, nullptr, Mtok, Dn, Fn, Fn, Dn, Dn, 0,0,0,0,0,0, 1);

    // 9) out = x1 + LN(y2)
    add_ln_kernel<<<Mtok, 128>>>(y2, x1, g2, be2, out);
}